// round 10
// baseline (speedup 1.0000x reference)
#include <cuda_runtime.h>
#include <cuda_fp16.h>
#include <cuda_bf16.h>

#define N_NODES 10000
#define E_EDGES 160000
#define EP (E_EDGES + N_NODES)   // 170000 (even -> exact warps in k_agg)
#define IN_CH 128
#define EMB 64
#define HEADS 12
#define HD (HEADS * EMB)          // 768
#define NEG_SLOPE 0.2f

// ---- scratch (device globals; no allocation allowed) ----
__device__ float  g_emb[N_NODES * EMB];
__device__ __half g_hh16[N_NODES * HD];        // fp16, only consumer: k_agg gather
__device__ float  g_asrc[N_NODES * HEADS];
__device__ float  g_adst[N_NODES * HEADS];
__device__ float  g_denom[N_NODES * HEADS];
__device__ float  g_eexp[EP * HEADS];
__device__ float  g_agg[N_NODES * EMB];
__device__ float  g_ws[EMB * HEADS];           // ws[k][h] = sum_d W[k,h*64+d]*att_src[h,d]
__device__ float  g_wd[EMB * HEADS];

// ---- f32x2 packed-FMA helpers ----
__device__ __forceinline__ unsigned long long pack2(float lo, float hi) {
    unsigned long long r;
    asm("mov.b64 %0, {%1, %2};" : "=l"(r) : "f"(lo), "f"(hi));
    return r;
}
__device__ __forceinline__ void unpack2(unsigned long long v, float& lo, float& hi) {
    asm("mov.b64 {%0, %1}, %2;" : "=f"(lo), "=f"(hi) : "l"(v));
}
__device__ __forceinline__ void fma2(unsigned long long& d,
                                     unsigned long long a, unsigned long long b) {
    asm("fma.rn.f32x2 %0, %1, %2, %0;" : "+l"(d) : "l"(a), "l"(b));
}

// ---- pass 0: tiny attention-weight contraction, 1 block ----
__global__ void __launch_bounds__(768) k_ws(const float* __restrict__ W,
                                            const float* __restrict__ att_src,
                                            const float* __restrict__ att_dst) {
    int t = threadIdx.x;                 // 768 = 64 k * 12 h
    int k = t / HEADS, h = t - k * HEADS;
    const float* wrow = W + (size_t)k * HD + h * EMB;
    const float* a1 = att_src + h * EMB;
    const float* a2 = att_dst + h * EMB;
    float s1 = 0.f, s2 = 0.f;
#pragma unroll 8
    for (int d = 0; d < EMB; d++) {
        float w = wrow[d];
        s1 += w * a1[d];
        s2 += w * a2[d];
    }
    g_ws[k * HEADS + h] = s1;
    g_wd[k * HEADS + h] = s2;
}

// ---- pass 1: zero scratch + emb = relu(x@We+be) + asrc/adst, 16 nodes/block ----
__global__ void __launch_bounds__(64) k_emb(const float* __restrict__ x,
                                            const float* __restrict__ We,
                                            const float* __restrict__ be) {
    __shared__ float sx[IN_CH][16];
    __shared__ float se[16][EMB + 1];    // padded: conflict-free row reads
    __shared__ float sws[EMB * HEADS];
    __shared__ float swd[EMB * HEADS];
    int n0 = blockIdx.x * 16;
    int t = threadIdx.x;                 // 0..63 = output channel
    int gt = blockIdx.x * 64 + t;        // 0..39999

    // zero g_agg (160000 float4) + g_denom (30000 float4); graph replays!
    float4 z = make_float4(0.f, 0.f, 0.f, 0.f);
    for (int i = gt; i < (N_NODES * EMB) / 4; i += 40000) ((float4*)g_agg)[i] = z;
    if (gt < (N_NODES * HEADS) / 4) ((float4*)g_denom)[gt] = z;

    for (int idx = t; idx < 16 * IN_CH; idx += 64) {
        int i = idx >> 7, k = idx & 127;
        sx[k][i] = x[(n0 + i) * IN_CH + k];
    }
    for (int idx = t; idx < EMB * HEADS; idx += 64) {
        sws[idx] = g_ws[idx];
        swd[idx] = g_wd[idx];
    }
    __syncthreads();

    float b = be[t];
    unsigned long long acc[8];
    unsigned long long binit = pack2(b, b);
#pragma unroll
    for (int j = 0; j < 8; j++) acc[j] = binit;
    for (int k = 0; k < IN_CH; k++) {
        float wv = We[k * EMB + t];
        unsigned long long w2 = pack2(wv, wv);
#pragma unroll
        for (int j = 0; j < 8; j++)
            fma2(acc[j], *(const unsigned long long*)&sx[k][2 * j], w2);
    }
#pragma unroll
    for (int j = 0; j < 8; j++) {
        float lo, hi;
        unpack2(acc[j], lo, hi);
        lo = fmaxf(lo, 0.f); hi = fmaxf(hi, 0.f);
        g_emb[(n0 + 2 * j) * EMB + t]     = lo;
        g_emb[(n0 + 2 * j + 1) * EMB + t] = hi;
        se[2 * j][t]     = lo;
        se[2 * j + 1][t] = hi;
    }
    __syncthreads();

    // asrc/adst: 16 nodes x 12 heads = 192 dot-products, 3 per thread
#pragma unroll
    for (int j = 0; j < 3; j++) {
        int p = t * 3 + j;
        int n = p / HEADS, h = p - n * HEADS;
        float s1 = 0.f, s2 = 0.f;
#pragma unroll 8
        for (int k = 0; k < EMB; k++) {
            float e = se[n][k];
            s1 += e * sws[k * HEADS + h];
            s2 += e * swd[k * HEADS + h];
        }
        g_asrc[(n0 + n) * HEADS + h] = s1;
        g_adst[(n0 + n) * HEADS + h] = s2;
    }
}

// ---- pass 2: edge exp/denom phase (grid-stride) + hh = emb@W (fp16) ----
__global__ void __launch_bounds__(768) k_hh(const float* __restrict__ W,
                                            const int* __restrict__ ei) {
    // phase 1: thread per (edge, head) over the whole grid (independent of GEMM)
    int t = threadIdx.x;
    int gt = blockIdx.x * 768 + t;                       // 480000 threads
    for (int idx = gt; idx < EP * HEADS; idx += 480000) {
        int e = idx / HEADS, h = idx - e * HEADS;
        int s, d;
        if (e < E_EDGES) { s = ei[e]; d = ei[E_EDGES + e]; }
        else             { s = d = e - E_EDGES; }
        float v = g_asrc[s * HEADS + h] + g_adst[d * HEADS + h];
        v = v > 0.f ? v : NEG_SLOPE * v;
        float ex = __expf(v);
        g_eexp[idx] = ex;
        atomicAdd(&g_denom[d * HEADS + h], ex);
    }

    // phase 2: GEMM hh = emb @ W, 16 nodes per block
    __shared__ float se[EMB][16];
    int n0 = blockIdx.x * 16;
    for (int idx = t; idx < 16 * EMB; idx += 768) {
        int i = idx >> 6, k = idx & 63;
        se[k][i] = g_emb[(n0 + i) * EMB + k];
    }
    __syncthreads();
    unsigned long long acc[8];
#pragma unroll
    for (int j = 0; j < 8; j++) acc[j] = 0ull;
    for (int k = 0; k < EMB; k++) {
        float wv = W[k * HD + t];
        unsigned long long w2 = pack2(wv, wv);
#pragma unroll
        for (int j = 0; j < 8; j++)
            fma2(acc[j], *(const unsigned long long*)&se[k][2 * j], w2);
    }
#pragma unroll
    for (int j = 0; j < 8; j++) {
        float lo, hi;
        unpack2(acc[j], lo, hi);
        g_hh16[(size_t)(n0 + 2 * j) * HD + t]     = __float2half_rn(lo);
        g_hh16[(size_t)(n0 + 2 * j + 1) * HD + t] = __float2half_rn(hi);
    }
}

// ---- pass 3: weighted aggregate. 2 edges/warp, 16 lanes/edge,
//      4 channels/lane, float4 atomics (RED.E.128). ----
__global__ void __launch_bounds__(256) k_agg(const int* __restrict__ ei) {
    int w = (blockIdx.x * blockDim.x + threadIdx.x) >> 5;
    int lane = threadIdx.x & 31;
    int half = lane >> 4;
    int l = lane & 15;
    int e = w * 2 + half;                                // EP even: always valid
    int s, d;
    if (e < E_EDGES) { s = ei[e]; d = ei[E_EDGES + e]; }
    else             { s = d = e - E_EDGES; }

    float wl = 0.f;
    if (l < HEADS)
        wl = __fdividef(g_eexp[e * HEADS + l],
                        g_denom[d * HEADS + l] + 1e-16f);

    const float2* __restrict__ hrow = (const float2*)(g_hh16 + (size_t)s * HD);
    float a0 = 0.f, a1 = 0.f, a2 = 0.f, a3 = 0.f;
#pragma unroll
    for (int h = 0; h < HEADS; h++) {
        float wv = __shfl_sync(0xffffffffu, wl, h, 16);
        float2 p = hrow[h * 16 + l];
        float2 f0 = __half22float2(*(const __half2*)&p.x);
        float2 f1 = __half22float2(*(const __half2*)&p.y);
        a0 += wv * f0.x; a1 += wv * f0.y;
        a2 += wv * f1.x; a3 += wv * f1.y;
    }
    atomicAdd((float4*)&g_agg[d * EMB + 4 * l], make_float4(a0, a1, a2, a3));
}

// ---- pass 4: out = relu(emb + mean_heads(agg) + bias) ----
__global__ void k_final(const float* __restrict__ bias, float* __restrict__ out) {
    int idx = blockIdx.x * blockDim.x + threadIdx.x;
    if (idx >= N_NODES * EMB) return;
    int c = idx & 63;
    out[idx] = fmaxf(g_emb[idx] + g_agg[idx] * (1.f / HEADS) + bias[c], 0.f);
}

extern "C" void kernel_launch(void* const* d_in, const int* in_sizes, int n_in,
                              void* d_out, int out_size) {
    const float* x    = (const float*)d_in[0];
    const int*   ei   = (const int*)d_in[1];
    const float* We   = (const float*)d_in[2];
    const float* be   = (const float*)d_in[3];
    const float* W    = (const float*)d_in[4];
    const float* asrc = (const float*)d_in[5];
    const float* adst = (const float*)d_in[6];
    const float* bias = (const float*)d_in[7];
    float* out = (float*)d_out;

    k_ws<<<1, 768>>>(W, asrc, adst);
    k_emb<<<N_NODES / 16, 64>>>(x, We, be);
    k_hh<<<N_NODES / 16, 768>>>(W, ei);
    k_agg<<<(EP / 2 * 32 + 255) / 256, 256>>>(ei);
    k_final<<<(N_NODES * EMB + 255) / 256, 256>>>(bias, out);
}

// round 13
// speedup vs baseline: 1.4012x; 1.4012x over previous
#include <cuda_runtime.h>
#include <cuda_fp16.h>
#include <cuda_bf16.h>

#define N_NODES 10000
#define E_EDGES 160000
#define EP (E_EDGES + N_NODES)   // 170000 (even -> exact warps in k_agg)
#define IN_CH 128
#define EMB 64
#define HEADS 12
#define HD (HEADS * EMB)          // 768
#define NEG_SLOPE 0.2f

// ---- scratch (device globals; no allocation allowed) ----
__device__ float  g_emb[N_NODES * EMB];
__device__ __half g_hh16[N_NODES * HD];        // fp16, only consumer: k_agg gather
__device__ float  g_asrc[N_NODES * HEADS];
__device__ float  g_adst[N_NODES * HEADS];
__device__ float  g_denom[N_NODES * HEADS];
__device__ float  g_eexp[EP * HEADS];
__device__ float  g_agg[N_NODES * EMB];

// ---- f32x2 packed-FMA helpers ----
__device__ __forceinline__ unsigned long long pack2(float lo, float hi) {
    unsigned long long r;
    asm("mov.b64 %0, {%1, %2};" : "=l"(r) : "f"(lo), "f"(hi));
    return r;
}
__device__ __forceinline__ void unpack2(unsigned long long v, float& lo, float& hi) {
    asm("mov.b64 {%0, %1}, %2;" : "=f"(lo), "=f"(hi) : "l"(v));
}
__device__ __forceinline__ void fma2(unsigned long long& d,
                                     unsigned long long a, unsigned long long b) {
    asm("fma.rn.f32x2 %0, %1, %2, %0;" : "+l"(d) : "l"(a), "l"(b));
}

// ---- pass 1: zero scratch (grid-stride) + emb = relu(x @ We + be) ----
__global__ void __launch_bounds__(64) k_emb(const float* __restrict__ x,
                                            const float* __restrict__ We,
                                            const float* __restrict__ be) {
    __shared__ float sx[IN_CH][16];
    int n0 = blockIdx.x * 16;
    int t = threadIdx.x;
    int gt = blockIdx.x * 64 + t;        // 0..39999

    // zero g_agg (160000 float4) + g_denom (30000 float4); graph replays!
    float4 z = make_float4(0.f, 0.f, 0.f, 0.f);
    for (int i = gt; i < (N_NODES * EMB) / 4; i += 40000) ((float4*)g_agg)[i] = z;
    if (gt < (N_NODES * HEADS) / 4) ((float4*)g_denom)[gt] = z;

    for (int idx = t; idx < 16 * IN_CH; idx += 64) {
        int i = idx >> 7, k = idx & 127;
        sx[k][i] = x[(n0 + i) * IN_CH + k];
    }
    __syncthreads();
    float b = be[t];
    unsigned long long acc[8];
    unsigned long long binit = pack2(b, b);
#pragma unroll
    for (int j = 0; j < 8; j++) acc[j] = binit;
    for (int k = 0; k < IN_CH; k++) {
        float wv = We[k * EMB + t];
        unsigned long long w2 = pack2(wv, wv);
#pragma unroll
        for (int j = 0; j < 8; j++)
            fma2(acc[j], *(const unsigned long long*)&sx[k][2 * j], w2);
    }
#pragma unroll
    for (int j = 0; j < 8; j++) {
        float lo, hi;
        unpack2(acc[j], lo, hi);
        g_emb[(n0 + 2 * j) * EMB + t]     = fmaxf(lo, 0.f);
        g_emb[(n0 + 2 * j + 1) * EMB + t] = fmaxf(hi, 0.f);
    }
}

// ---- pass 2: hh = emb @ W (fp16 out) + fp32 logits, 16 nodes/block ----
__global__ void __launch_bounds__(768) k_hh(const float* __restrict__ W,
                                            const float* __restrict__ att_src,
                                            const float* __restrict__ att_dst) {
    __shared__ float se[EMB][16];
    __shared__ float ssrc[16][HEADS];
    __shared__ float sdst[16][HEADS];
    int n0 = blockIdx.x * 16;
    int t = threadIdx.x;
    for (int idx = t; idx < 16 * EMB; idx += 768) {
        int i = idx >> 6, k = idx & 63;
        se[k][i] = g_emb[(n0 + i) * EMB + k];
    }
    if (t < 16 * HEADS) {
        ((float*)ssrc)[t] = 0.f;
        ((float*)sdst)[t] = 0.f;
    }
    __syncthreads();
    unsigned long long acc[8];
#pragma unroll
    for (int j = 0; j < 8; j++) acc[j] = 0ull;
    for (int k = 0; k < EMB; k++) {
        float wv = W[k * HD + t];
        unsigned long long w2 = pack2(wv, wv);
#pragma unroll
        for (int j = 0; j < 8; j++)
            fma2(acc[j], *(const unsigned long long*)&se[k][2 * j], w2);
    }
    float av[16];
#pragma unroll
    for (int j = 0; j < 8; j++) unpack2(acc[j], av[2 * j], av[2 * j + 1]);

    float as = att_src[t], ad = att_dst[t];
    int h = t >> 6;
#pragma unroll
    for (int i = 0; i < 16; i++) {
        g_hh16[(size_t)(n0 + i) * HD + t] = __float2half_rn(av[i]);
        float ps = av[i] * as;
        float pd = av[i] * ad;
#pragma unroll
        for (int off = 16; off; off >>= 1) {
            ps += __shfl_down_sync(0xffffffffu, ps, off);
            pd += __shfl_down_sync(0xffffffffu, pd, off);
        }
        if ((t & 31) == 0) {
            atomicAdd(&ssrc[i][h], ps);
            atomicAdd(&sdst[i][h], pd);
        }
    }
    __syncthreads();
    if (t < 16 * HEADS) {
        int i = t / HEADS, hh_ = t % HEADS;
        g_asrc[(n0 + i) * HEADS + hh_] = ssrc[i][hh_];
        g_adst[(n0 + i) * HEADS + hh_] = sdst[i][hh_];
    }
}

// ---- pass 3: thread per (edge, head): exp(leaky(logit)), atomic denom ----
__global__ void k_sum(const int* __restrict__ ei) {
    int idx = blockIdx.x * blockDim.x + threadIdx.x;
    if (idx >= EP * HEADS) return;
    int e = idx / HEADS, h = idx - e * HEADS;
    int s, d;
    if (e < E_EDGES) { s = ei[e]; d = ei[E_EDGES + e]; }
    else             { s = d = e - E_EDGES; }
    float v = g_asrc[s * HEADS + h] + g_adst[d * HEADS + h];
    v = v > 0.f ? v : NEG_SLOPE * v;
    float ex = __expf(v);
    g_eexp[idx] = ex;
    atomicAdd(&g_denom[d * HEADS + h], ex);
}

// ---- pass 4: weighted aggregate. 2 edges/warp, 16 lanes/edge,
//      4 channels/lane, float4 atomics (RED.E.128), fdividef norm ----
__global__ void __launch_bounds__(256) k_agg(const int* __restrict__ ei) {
    int w = (blockIdx.x * blockDim.x + threadIdx.x) >> 5;
    int lane = threadIdx.x & 31;
    int half = lane >> 4;
    int l = lane & 15;
    int e = w * 2 + half;                                // EP even: always valid
    int s, d;
    if (e < E_EDGES) { s = ei[e]; d = ei[E_EDGES + e]; }
    else             { s = d = e - E_EDGES; }

    float wl = 0.f;
    if (l < HEADS)
        wl = __fdividef(g_eexp[e * HEADS + l],
                        g_denom[d * HEADS + l] + 1e-16f);

    const float2* __restrict__ hrow = (const float2*)(g_hh16 + (size_t)s * HD);
    float a0 = 0.f, a1 = 0.f, a2 = 0.f, a3 = 0.f;
#pragma unroll
    for (int h = 0; h < HEADS; h++) {
        float wv = __shfl_sync(0xffffffffu, wl, h, 16);
        float2 p = hrow[h * 16 + l];
        float2 f0 = __half22float2(*(const __half2*)&p.x);
        float2 f1 = __half22float2(*(const __half2*)&p.y);
        a0 += wv * f0.x; a1 += wv * f0.y;
        a2 += wv * f1.x; a3 += wv * f1.y;
    }
    atomicAdd((float4*)&g_agg[d * EMB + 4 * l], make_float4(a0, a1, a2, a3));
}

// ---- pass 5: out = relu(emb + mean_heads(agg) + bias), float4 ----
__global__ void k_final(const float* __restrict__ bias, float* __restrict__ out) {
    int idx = blockIdx.x * blockDim.x + threadIdx.x;   // float4 index
    if (idx >= (N_NODES * EMB) / 4) return;
    int c4 = idx & 15;                                  // float4 within 64-ch row
    float4 eb = ((const float4*)g_emb)[idx];
    float4 ag = ((const float4*)g_agg)[idx];
    float4 bi = ((const float4*)bias)[c4];
    float4 r;
    r.x = fmaxf(eb.x + ag.x * (1.f / HEADS) + bi.x, 0.f);
    r.y = fmaxf(eb.y + ag.y * (1.f / HEADS) + bi.y, 0.f);
    r.z = fmaxf(eb.z + ag.z * (1.f / HEADS) + bi.z, 0.f);
    r.w = fmaxf(eb.w + ag.w * (1.f / HEADS) + bi.w, 0.f);
    ((float4*)out)[idx] = r;
}

extern "C" void kernel_launch(void* const* d_in, const int* in_sizes, int n_in,
                              void* d_out, int out_size) {
    const float* x    = (const float*)d_in[0];
    const int*   ei   = (const int*)d_in[1];
    const float* We   = (const float*)d_in[2];
    const float* be   = (const float*)d_in[3];
    const float* W    = (const float*)d_in[4];
    const float* asrc = (const float*)d_in[5];
    const float* adst = (const float*)d_in[6];
    const float* bias = (const float*)d_in[7];
    float* out = (float*)d_out;

    k_emb<<<N_NODES / 16, 64>>>(x, We, be);
    k_hh<<<N_NODES / 16, 768>>>(W, asrc, adst);
    k_sum<<<(EP * HEADS + 255) / 256, 256>>>(ei);
    k_agg<<<(EP / 2 * 32 + 255) / 256, 256>>>(ei);
    k_final<<<(N_NODES * EMB / 4 + 255) / 256, 256>>>(bias, out);
}